// round 2
// baseline (speedup 1.0000x reference)
#include <cuda_runtime.h>
#include <cstdint>

// All2AllDenseEmbedding with gpu_num=1 == plain row gather:
//   out[row][:] = table[idx[row]][:]   for row in [0, 4096*26*2)
// Each table row is 32 fp32 = 128 bytes = exactly one cache line.
// 8 threads per row, one float4 (LDG.128 / STG.128) each.
//
// Index dtype is ambiguous (reference is int64; harness may pass int32).
// A probe kernel inspects the high 32 bits of the first 2048 8-byte words:
// all-zero  -> int64 layout; any nonzero -> int32 layout.

static constexpr int  EMB_DIM      = 32;
static constexpr long NROWS        = 4096L * 26L * 2L;   // 212992
static constexpr int  THREADS      = 256;
static constexpr int  VECS_PER_ROW = EMB_DIM / 4;        // 8 float4 per row

__device__ int g_idx_is_i32;   // 1 if indices are int32, 0 if int64

__global__ void probe_idx_dtype_kernel(const unsigned int* __restrict__ idx_raw)
{
    // Single block. Examine words [0, 2048): high half of each 8-byte pair.
    // int32 buffer has 212992 ints -> reading 4096 ints is in-bounds.
    // int64 buffer has 212992 longs -> also in-bounds.
    __shared__ int s_or[THREADS];
    unsigned int acc = 0;
    for (int i = threadIdx.x; i < 2048; i += THREADS)
        acc |= idx_raw[2 * i + 1];
    s_or[threadIdx.x] = (acc != 0);
    __syncthreads();
    for (int s = THREADS / 2; s > 0; s >>= 1) {
        if (threadIdx.x < s) s_or[threadIdx.x] |= s_or[threadIdx.x + s];
        __syncthreads();
    }
    if (threadIdx.x == 0) g_idx_is_i32 = s_or[0];
}

__global__ __launch_bounds__(THREADS)
void gather_rows_kernel(const void*   __restrict__ idx_raw,
                        const float4* __restrict__ table,
                        float4*       __restrict__ out)
{
    long t = (long)blockIdx.x * THREADS + threadIdx.x;   // one float4 per thread
    long row  = t >> 3;        // t / 8
    int  lane = (int)(t & 7);  // t % 8
    if (row >= NROWS) return;

    long r;
    if (g_idx_is_i32) {
        r = (long)__ldg(((const int*)idx_raw) + row);
    } else {
        r = (long)__ldg(((const long long*)idx_raw) + row);
    }
    out[row * VECS_PER_ROW + lane] = __ldg(table + r * VECS_PER_ROW + lane);
}

extern "C" void kernel_launch(void* const* d_in, const int* in_sizes, int n_in,
                              void* d_out, int out_size)
{
    // Pick the index tensor by element count (212992 vs 32,000,000).
    const void*  idx;
    const float* table;
    if (in_sizes[0] == (int)NROWS) {
        idx   = d_in[0];
        table = (const float*)d_in[1];
    } else {
        idx   = d_in[1];
        table = (const float*)d_in[0];
    }

    probe_idx_dtype_kernel<<<1, THREADS>>>((const unsigned int*)idx);

    long total_threads = NROWS * VECS_PER_ROW;                      // 1,703,936
    int  blocks = (int)((total_threads + THREADS - 1) / THREADS);   // 6656
    gather_rows_kernel<<<blocks, THREADS>>>(idx, (const float4*)table, (float4*)d_out);
}

// round 3
// speedup vs baseline: 1.0226x; 1.0226x over previous
#include <cuda_runtime.h>
#include <cstdint>

// All2AllDenseEmbedding with gpu_num=1 == plain row gather:
//   out[row][:] = table[idx[row]][:]   for row in [0, 4096*26*2)
// Each table row is 32 fp32 = 128 bytes = one cache line.
// 8 threads per row, one float4 each; BATCH=4 elements per thread with
// phase-separated loads to expose MLP=4 (latency was the R2 bottleneck).

static constexpr int  EMB_DIM      = 32;
static constexpr long NROWS        = 4096L * 26L * 2L;     // 212992
static constexpr int  THREADS      = 256;
static constexpr int  VECS_PER_ROW = EMB_DIM / 4;          // 8
static constexpr long TOTAL_VECS   = NROWS * VECS_PER_ROW; // 1,703,936
static constexpr int  BATCH        = 4;
// TOTAL_VECS / (THREADS*BATCH) = 1664 exactly — no tail.
static constexpr int  BLOCKS       = (int)(TOTAL_VECS / (THREADS * BATCH));

__device__ int g_idx_is_i32;   // 1 if indices are int32, 0 if int64

__global__ void probe_idx_dtype_kernel(const unsigned int* __restrict__ idx_raw)
{
    // High half of each 8-byte pair: all-zero over 2048 words -> int64.
    unsigned int acc = 0;
    for (int i = threadIdx.x; i < 2048; i += THREADS)
        acc |= idx_raw[2 * i + 1];
    int any = __syncthreads_or(acc != 0);
    if (threadIdx.x == 0) g_idx_is_i32 = any;
}

__global__ __launch_bounds__(THREADS)
void gather_rows_kernel(const void*   __restrict__ idx_raw,
                        const float4* __restrict__ table,
                        float4*       __restrict__ out)
{
    const long stride = (long)BLOCKS * THREADS;
    const long t0     = (long)blockIdx.x * THREADS + threadIdx.x;
    const bool is32   = (g_idx_is_i32 != 0);

    long row[BATCH];
    int  lane[BATCH];
#pragma unroll
    for (int b = 0; b < BATCH; b++) {
        long t  = t0 + b * stride;
        row[b]  = t >> 3;
        lane[b] = (int)(t & 7);
    }

    // Phase 1: 4 independent index loads
    long r[BATCH];
    if (is32) {
        const int* ip = (const int*)idx_raw;
#pragma unroll
        for (int b = 0; b < BATCH; b++) r[b] = (long)__ldg(ip + row[b]);
    } else {
        const long long* lp = (const long long*)idx_raw;
#pragma unroll
        for (int b = 0; b < BATCH; b++) r[b] = (long)__ldg(lp + row[b]);
    }

    // Phase 2: 4 independent gathers
    float4 v[BATCH];
#pragma unroll
    for (int b = 0; b < BATCH; b++)
        v[b] = __ldg(table + r[b] * VECS_PER_ROW + lane[b]);

    // Phase 3: 4 coalesced stores
#pragma unroll
    for (int b = 0; b < BATCH; b++)
        out[row[b] * VECS_PER_ROW + lane[b]] = v[b];
}

extern "C" void kernel_launch(void* const* d_in, const int* in_sizes, int n_in,
                              void* d_out, int out_size)
{
    // Pick the index tensor by element count (212992 vs 32,000,000).
    const void*  idx;
    const float* table;
    if (in_sizes[0] == (int)NROWS) {
        idx   = d_in[0];
        table = (const float*)d_in[1];
    } else {
        idx   = d_in[1];
        table = (const float*)d_in[0];
    }

    probe_idx_dtype_kernel<<<1, THREADS>>>((const unsigned int*)idx);
    gather_rows_kernel<<<BLOCKS, THREADS>>>(idx, (const float4*)table, (float4*)d_out);
}

// round 4
// speedup vs baseline: 1.2143x; 1.1875x over previous
#include <cuda_runtime.h>
#include <cstdint>

// Row gather: out[row][:] = table[idx[row]][:], row in [0, 212992), row = 128B.
// One warp owns 32 rows: coalesced per-lane index load, shfl distribution,
// 8 independent float4 gathers per thread (MLP=8), 8 coalesced stores.
// Index dtype (int32 vs int64) probed per-block from the first 32 8-byte
// pairs (high words all zero => int64), fused into the same kernel.

static constexpr int  EMB_DIM      = 32;
static constexpr long NROWS        = 4096L * 26L * 2L;   // 212992
static constexpr int  THREADS      = 256;
static constexpr int  VECS_PER_ROW = EMB_DIM / 4;        // 8
static constexpr int  ROWS_PER_BLOCK = THREADS / 32 * 32;  // 8 warps * 32 rows = 256
static constexpr int  BLOCKS       = (int)(NROWS / ROWS_PER_BLOCK);  // 832, exact

__global__ __launch_bounds__(THREADS)
void gather_rows_kernel(const void*   __restrict__ idx_raw,
                        const float4* __restrict__ table,
                        float4*       __restrict__ out)
{
    // ---- fused dtype probe (per block, L2-hit after first block) ----
    unsigned int hi = 0;
    if (threadIdx.x < 32)
        hi = ((const unsigned int*)idx_raw)[2 * threadIdx.x + 1];
    const bool is32 = (__syncthreads_or(hi != 0) != 0);

    const int  warp = threadIdx.x >> 5;
    const int  lane = threadIdx.x & 31;
    const long rowBase = ((long)blockIdx.x * 8 + warp) * 32;

    // ---- one coalesced index load per lane ----
    long long myIdx;
    if (is32) myIdx = (long long)__ldg(((const int*)idx_raw) + rowBase + lane);
    else      myIdx = __ldg(((const long long*)idx_raw) + rowBase + lane);

    const int subrow = lane >> 3;   // 0..3: which of 4 rows this step
    const int col    = lane & 7;    // float4 slot within row

    // ---- distribute indices: step s covers rows rowBase + s*4 .. +3 ----
    long r[8];
#pragma unroll
    for (int s = 0; s < 8; s++)
        r[s] = (long)__shfl_sync(0xffffffffu, myIdx, s * 4 + subrow);

    // ---- 8 independent gathers (MLP=8) ----
    float4 v[8];
#pragma unroll
    for (int s = 0; s < 8; s++)
        v[s] = __ldg(table + r[s] * VECS_PER_ROW + col);

    // ---- 8 coalesced stores (512B contiguous per warp per step) ----
#pragma unroll
    for (int s = 0; s < 8; s++)
        out[(rowBase + s * 4 + subrow) * VECS_PER_ROW + col] = v[s];
}

extern "C" void kernel_launch(void* const* d_in, const int* in_sizes, int n_in,
                              void* d_out, int out_size)
{
    // Pick the index tensor by element count (212992 vs 32,000,000).
    const void*  idx;
    const float* table;
    if (in_sizes[0] == (int)NROWS) {
        idx   = d_in[0];
        table = (const float*)d_in[1];
    } else {
        idx   = d_in[1];
        table = (const float*)d_in[0];
    }

    gather_rows_kernel<<<BLOCKS, THREADS>>>(idx, (const float4*)table, (float4*)d_out);
}